// round 7
// baseline (speedup 1.0000x reference)
#include <cuda_runtime.h>
#include <cuda_bf16.h>

#define TLEN 2048
#define NTH 512                    // one thread per 4-element chunk; one sequence per block
#define NWARP (NTH / 32)           // 16 warps

struct M2 { float a, b, c, d; };
__device__ __forceinline__ M2 mmul(M2 X, M2 Y) {   // X*Y
    M2 r;
    r.a = fmaf(X.a, Y.a, X.b * Y.c);
    r.b = fmaf(X.a, Y.b, X.b * Y.d);
    r.c = fmaf(X.c, Y.a, X.d * Y.c);
    r.d = fmaf(X.c, Y.b, X.d * Y.d);
    return r;
}

__global__ __launch_bounds__(NTH) void physics_scan_kernel(
    const float* __restrict__ u,
    const float* __restrict__ p_dt, const float* __restrict__ p_m,
    const float* __restrict__ p_c,  const float* __restrict__ p_k,
    const float* __restrict__ p_im, const float* __restrict__ p_is,
    const float* __restrict__ p_om, const float* __restrict__ p_os,
    float* __restrict__ out, int Bsz)
{
    __shared__ float2 stot[NWARP];   // warp inclusive totals
    __shared__ float2 sinc[NWARP];   // warp incoming states

    const int tid  = threadIdx.x;
    const int lane = tid & 31;
    const int w    = tid >> 5;

    const float dt = *p_dt, m = *p_m, cc = *p_c, k = *p_k;
    const float in_mean = *p_im, in_std = *p_is;
    const float out_mean = *p_om, out_std = *p_os;
    const float inv_m = 1.0f / m;
    const float ios   = 1.0f / out_std;
    const float a1 = -k * inv_m;
    const float a2 = -cc * inv_m;
    const float s1 = in_std * inv_m;          // g = u*s1 + s0  (= u_p/m)
    const float s0 = in_mean * inv_m;
    const float q1 = a1 * ios, q2 = a2 * ios, q0 = -out_mean * ios;

    M2 A; A.a = 1.0f; A.b = dt; A.c = dt * a1; A.d = 1.0f + dt * a2;

    // folded recurrence: v' = Ac*x + Ad*v + dt*g,  x' = x + dt*v
    const float gd1 = dt * s1, gd0 = dt * s0;         // dt*g = u*gd1 + gd0
    const float r1  = ios * s1;                       // ios*g + q0 = u*r1 + r0
    const float r0  = fmaf(ios, s0, q0);

    // ---- Load chunk (one coalesced LDG.128 per thread) ----
    const size_t goff = (size_t)blockIdx.x * TLEN + (size_t)tid * 4;
    float4 uu = *reinterpret_cast<const float4*>(u + goff);

    // ---- Pass 1: 4-step recurrence from zero state; y0 into registers ----
    float x = 0.0f, v = 0.0f;
    float4 yy;
    {
        float vn = fmaf(A.c, x, fmaf(A.d, v, fmaf(uu.x, gd1, gd0)));
        float xn = fmaf(dt, v, x);
        x = xn; v = vn;
        yy.x = fmaf(q1, x, fmaf(q2, v, fmaf(uu.x, r1, r0)));
    }
    {
        float vn = fmaf(A.c, x, fmaf(A.d, v, fmaf(uu.y, gd1, gd0)));
        float xn = fmaf(dt, v, x);
        x = xn; v = vn;
        yy.y = fmaf(q1, x, fmaf(q2, v, fmaf(uu.y, r1, r0)));
    }
    {
        float vn = fmaf(A.c, x, fmaf(A.d, v, fmaf(uu.z, gd1, gd0)));
        float xn = fmaf(dt, v, x);
        x = xn; v = vn;
        yy.z = fmaf(q1, x, fmaf(q2, v, fmaf(uu.z, r1, r0)));
    }
    {
        float vn = fmaf(A.c, x, fmaf(A.d, v, fmaf(uu.w, gd1, gd0)));
        float xn = fmaf(dt, v, x);
        x = xn; v = vn;
        yy.w = fmaf(q1, x, fmaf(q2, v, fmaf(uu.w, r1, r0)));
    }

    // ---- Matrix powers: A^2..A^4, then P[s] = A^(4*2^s), s=0..4 (A^4..A^64) ----
    M2 A2 = mmul(A, A);
    M2 A3 = mmul(A2, A);
    M2 P[5];
    P[0] = mmul(A2, A2);                       // A^4
    #pragma unroll
    for (int s = 1; s < 5; s++) P[s] = mmul(P[s - 1], P[s - 1]);

    // ---- Warp Kogge-Stone scan of chunk offsets (matrices lane-common) ----
    float bx = x, bv = v;
    #pragma unroll
    for (int s = 0; s < 5; s++) {
        int d = 1 << s;
        float ox = __shfl_up_sync(0xffffffffu, bx, d);
        float ov = __shfl_up_sync(0xffffffffu, bv, d);
        if (lane >= d) {
            bx = fmaf(P[s].a, ox, fmaf(P[s].b, ov, bx));
            bv = fmaf(P[s].c, ox, fmaf(P[s].d, ov, bv));
        }
    }
    float ex = __shfl_up_sync(0xffffffffu, bx, 1);
    float ev = __shfl_up_sync(0xffffffffu, bv, 1);
    if (lane == 0) { ex = 0.0f; ev = 0.0f; }

    if (lane == 31) stot[w] = make_float2(bx, bv);
    __syncthreads();

    // ---- Warp 0: 16-lane scan of warp totals with A^(128*2^s) ----
    if (tid < NWARP) {
        float2 t = stot[tid];
        float ix = t.x, iv = t.y;
        M2 W = mmul(P[4], P[4]);               // A^128
        #pragma unroll
        for (int s = 0; s < 4; s++) {
            int d = 1 << s;
            float ox = __shfl_up_sync(0x0000ffffu, ix, d);
            float ov = __shfl_up_sync(0x0000ffffu, iv, d);
            if (tid >= d) {
                ix = fmaf(W.a, ox, fmaf(W.b, ov, ix));
                iv = fmaf(W.c, ox, fmaf(W.d, ov, iv));
            }
            if (s < 3) W = mmul(W, W);
        }
        float jx = __shfl_up_sync(0x0000ffffu, ix, 1);
        float jv = __shfl_up_sync(0x0000ffffu, iv, 1);
        if (tid == 0) { jx = 0.0f; jv = 0.0f; }
        sinc[tid] = make_float2(jx, jv);
        if (tid == NWARP - 1) {                // s_T (state0 = 0)
            float2* stout = reinterpret_cast<float2*>(out + (size_t)Bsz * TLEN);
            stout[blockIdx.x] = make_float2(ix, iv);
        }
    }
    __syncthreads();

    // ---- Chunk start state: A^(4*lane) * W_in + exclusive-lane offset ----
    float2 Wi = sinc[w];
    float wx = Wi.x, wv = Wi.y;
    #pragma unroll
    for (int b = 0; b < 5; b++) {
        if (lane & (1 << b)) {
            float nx = fmaf(P[b].a, wx, P[b].b * wv);
            float nv = fmaf(P[b].c, wx, P[b].d * wv);
            wx = nx; wv = nv;
        }
    }
    const float sx = ex + wx, sv = ev + wv;

    // ---- Correction coefficients (q1,q2)·A^{i+1}, i=0..3, in registers ----
    float ca0 = fmaf(q1, A.a,    q2 * A.c),    cb0 = fmaf(q1, A.b,    q2 * A.d);
    float ca1 = fmaf(q1, A2.a,   q2 * A2.c),   cb1 = fmaf(q1, A2.b,   q2 * A2.d);
    float ca2 = fmaf(q1, A3.a,   q2 * A3.c),   cb2 = fmaf(q1, A3.b,   q2 * A3.d);
    float ca3 = fmaf(q1, P[0].a, q2 * P[0].c), cb3 = fmaf(q1, P[0].b, q2 * P[0].d);

    yy.x = fmaf(ca0, sx, fmaf(cb0, sv, yy.x));
    yy.y = fmaf(ca1, sx, fmaf(cb1, sv, yy.y));
    yy.z = fmaf(ca2, sx, fmaf(cb2, sv, yy.z));
    yy.w = fmaf(ca3, sx, fmaf(cb3, sv, yy.w));

    // ---- Coalesced STG.128 ----
    *reinterpret_cast<float4*>(out + goff) = yy;
}

extern "C" void kernel_launch(void* const* d_in, const int* in_sizes, int n_in,
                              void* d_out, int out_size) {
    const float* u = (const float*)d_in[0];
    int Bsz = in_sizes[0] / TLEN;
    dim3 grid(Bsz);
    physics_scan_kernel<<<grid, NTH>>>(
        u,
        (const float*)d_in[1], (const float*)d_in[2], (const float*)d_in[3],
        (const float*)d_in[4], (const float*)d_in[5], (const float*)d_in[6],
        (const float*)d_in[7], (const float*)d_in[8],
        (float*)d_out, Bsz);
}

// round 8
// speedup vs baseline: 1.5933x; 1.5933x over previous
#include <cuda_runtime.h>
#include <cuda_bf16.h>

#define TLEN 2048
#define CH 8                        // elements per thread (contiguous chunk)
#define NTH 256                     // one sequence per block
#define NWARP (NTH / 32)            // 8 warps

struct M2 { float a, b, c, d; };
__device__ __forceinline__ M2 mmul(M2 X, M2 Y) {   // X*Y
    M2 r;
    r.a = fmaf(X.a, Y.a, X.b * Y.c);
    r.b = fmaf(X.a, Y.b, X.b * Y.d);
    r.c = fmaf(X.c, Y.a, X.d * Y.c);
    r.d = fmaf(X.c, Y.b, X.d * Y.d);
    return r;
}
__device__ __forceinline__ float4 m2f4(M2 X) { return make_float4(X.a, X.b, X.c, X.d); }

struct Tables {
    float4 c0;        // gd1, gd0, r1, r0
    float4 c1;        // dt, Ac, Ad, q1
    float4 c2;        // q2, 0, 0, 0
    float4 P[5];      // A^(8*2^s), s=0..4  (A^8..A^128)
    float4 W[3];      // A^(256*2^s), s=0..2 (A^256..A^1024)
    float4 ca[2];     // correction alpha_i, i=0..7
    float4 cb[2];     // correction beta_i,  i=0..7
};
__device__ Tables g_tab;

__global__ void prep_kernel(
    const float* p_dt, const float* p_m, const float* p_c, const float* p_k,
    const float* p_im, const float* p_is, const float* p_om, const float* p_os)
{
    const float dt = *p_dt, m = *p_m, cc = *p_c, k = *p_k;
    const float inv_m = 1.0f / m;
    const float ios   = 1.0f / (*p_os);
    const float a1 = -k * inv_m;
    const float a2 = -cc * inv_m;
    const float s1 = (*p_is) * inv_m;
    const float s0 = (*p_im) * inv_m;
    const float q1 = a1 * ios, q2 = a2 * ios, q0 = -(*p_om) * ios;

    M2 A; A.a = 1.0f; A.b = dt; A.c = dt * a1; A.d = 1.0f + dt * a2;

    g_tab.c0 = make_float4(dt * s1, dt * s0, ios * s1, fmaf(ios, s0, q0));
    g_tab.c1 = make_float4(dt, A.c, A.d, q1);
    g_tab.c2 = make_float4(q2, 0.f, 0.f, 0.f);

    // corrections (q1,q2)*A^{i+1}, i=0..7; afterwards M = A^8
    float ca[8], cb[8];
    M2 M = A;
    #pragma unroll
    for (int i = 0; i < 8; i++) {
        ca[i] = fmaf(q1, M.a, q2 * M.c);
        cb[i] = fmaf(q1, M.b, q2 * M.d);
        if (i < 7) M = mmul(A, M);
    }
    g_tab.ca[0] = make_float4(ca[0], ca[1], ca[2], ca[3]);
    g_tab.ca[1] = make_float4(ca[4], ca[5], ca[6], ca[7]);
    g_tab.cb[0] = make_float4(cb[0], cb[1], cb[2], cb[3]);
    g_tab.cb[1] = make_float4(cb[4], cb[5], cb[6], cb[7]);

    M2 Q = M;                      // A^8
    #pragma unroll
    for (int s = 0; s < 5; s++) { g_tab.P[s] = m2f4(Q); Q = mmul(Q, Q); }
    // Q = A^256 now
    #pragma unroll
    for (int s = 0; s < 3; s++) { g_tab.W[s] = m2f4(Q); Q = mmul(Q, Q); }
}

__global__ __launch_bounds__(NTH) void physics_scan_kernel(
    const float* __restrict__ u, float* __restrict__ out, int Bsz)
{
    __shared__ float2 stot[NWARP];
    __shared__ float2 sinc[NWARP];

    const int tid  = threadIdx.x;
    const int lane = tid & 31;
    const int w    = tid >> 5;

    const float4 c0 = g_tab.c0;           // gd1, gd0, r1, r0
    const float4 c1 = g_tab.c1;           // dt, Ac, Ad, q1
    const float  q2 = g_tab.c2.x;
    const float gd1 = c0.x, gd0 = c0.y, r1 = c0.z, r0 = c0.w;
    const float dt = c1.x, Ac = c1.y, Ad = c1.z, q1 = c1.w;

    const size_t goff = (size_t)blockIdx.x * TLEN + (size_t)tid * CH;
    float4 u0 = *reinterpret_cast<const float4*>(u + goff);
    float4 u1 = *reinterpret_cast<const float4*>(u + goff + 4);

    // ---- Pass 1: 8-step recurrence from zero state; y0 in registers ----
    float x = 0.0f, v = 0.0f;
    float4 y0, y1;
    #define STEP(UE, YE)                                               \
    {                                                                  \
        float t  = fmaf(UE, gd1, gd0);                                 \
        float vn = fmaf(Ac, x, fmaf(Ad, v, t));                        \
        float xn = fmaf(dt, v, x);                                     \
        x = xn; v = vn;                                                \
        YE = fmaf(q1, x, fmaf(q2, v, fmaf(UE, r1, r0)));               \
    }
    STEP(u0.x, y0.x) STEP(u0.y, y0.y) STEP(u0.z, y0.z) STEP(u0.w, y0.w)
    STEP(u1.x, y1.x) STEP(u1.y, y1.y) STEP(u1.z, y1.z) STEP(u1.w, y1.w)
    #undef STEP

    // ---- Load scan matrices (uniform, L1/L2 broadcast) ----
    float4 P[5];
    #pragma unroll
    for (int s = 0; s < 5; s++) P[s] = g_tab.P[s];

    // ---- Warp Kogge-Stone scan of chunk offsets (matrices lane-common) ----
    float bx = x, bv = v;
    #pragma unroll
    for (int s = 0; s < 5; s++) {
        int d = 1 << s;
        float ox = __shfl_up_sync(0xffffffffu, bx, d);
        float ov = __shfl_up_sync(0xffffffffu, bv, d);
        if (lane >= d) {
            bx = fmaf(P[s].x, ox, fmaf(P[s].y, ov, bx));
            bv = fmaf(P[s].z, ox, fmaf(P[s].w, ov, bv));
        }
    }
    float ex = __shfl_up_sync(0xffffffffu, bx, 1);
    float ev = __shfl_up_sync(0xffffffffu, bv, 1);
    if (lane == 0) { ex = 0.0f; ev = 0.0f; }

    if (lane == 31) stot[w] = make_float2(bx, bv);
    __syncthreads();

    // ---- Warp 0: 8-lane scan of warp totals with A^(256*2^s) ----
    if (tid < NWARP) {
        float2 t = stot[tid];
        float ix = t.x, iv = t.y;
        #pragma unroll
        for (int s = 0; s < 3; s++) {
            int d = 1 << s;
            float4 Wm = g_tab.W[s];
            float ox = __shfl_up_sync(0x000000ffu, ix, d);
            float ov = __shfl_up_sync(0x000000ffu, iv, d);
            if (tid >= d) {
                ix = fmaf(Wm.x, ox, fmaf(Wm.y, ov, ix));
                iv = fmaf(Wm.z, ox, fmaf(Wm.w, ov, iv));
            }
        }
        float jx = __shfl_up_sync(0x000000ffu, ix, 1);
        float jv = __shfl_up_sync(0x000000ffu, iv, 1);
        if (tid == 0) { jx = 0.0f; jv = 0.0f; }
        sinc[tid] = make_float2(jx, jv);
        if (tid == NWARP - 1) {            // s_T = inclusive total (state0 = 0)
            float2* stout = reinterpret_cast<float2*>(out + (size_t)Bsz * TLEN);
            stout[blockIdx.x] = make_float2(ix, iv);
        }
    }
    __syncthreads();

    // ---- Chunk start state: A^(8*lane) * W_in + exclusive-lane offset ----
    float2 Wi = sinc[w];
    float wx = Wi.x, wv = Wi.y;
    #pragma unroll
    for (int b = 0; b < 5; b++) {
        if (lane & (1 << b)) {
            float nx = fmaf(P[b].x, wx, P[b].y * wv);
            float nv = fmaf(P[b].z, wx, P[b].w * wv);
            wx = nx; wv = nv;
        }
    }
    const float sx = ex + wx, sv = ev + wv;

    // ---- Fused affine correction: y_i = y0_i + ca_i*sx + cb_i*sv ----
    float4 caA = g_tab.ca[0], caB = g_tab.ca[1];
    float4 cbA = g_tab.cb[0], cbB = g_tab.cb[1];

    y0.x = fmaf(caA.x, sx, fmaf(cbA.x, sv, y0.x));
    y0.y = fmaf(caA.y, sx, fmaf(cbA.y, sv, y0.y));
    y0.z = fmaf(caA.z, sx, fmaf(cbA.z, sv, y0.z));
    y0.w = fmaf(caA.w, sx, fmaf(cbA.w, sv, y0.w));
    y1.x = fmaf(caB.x, sx, fmaf(cbB.x, sv, y1.x));
    y1.y = fmaf(caB.y, sx, fmaf(cbB.y, sv, y1.y));
    y1.z = fmaf(caB.z, sx, fmaf(cbB.z, sv, y1.z));
    y1.w = fmaf(caB.w, sx, fmaf(cbB.w, sv, y1.w));

    *reinterpret_cast<float4*>(out + goff)     = y0;
    *reinterpret_cast<float4*>(out + goff + 4) = y1;
}

extern "C" void kernel_launch(void* const* d_in, const int* in_sizes, int n_in,
                              void* d_out, int out_size) {
    const float* u = (const float*)d_in[0];
    int Bsz = in_sizes[0] / TLEN;
    prep_kernel<<<1, 1>>>(
        (const float*)d_in[1], (const float*)d_in[2], (const float*)d_in[3],
        (const float*)d_in[4], (const float*)d_in[5], (const float*)d_in[6],
        (const float*)d_in[7], (const float*)d_in[8]);
    physics_scan_kernel<<<Bsz, NTH>>>(u, (float*)d_out, Bsz);
}

// round 9
// speedup vs baseline: 1.9068x; 1.1967x over previous
#include <cuda_runtime.h>
#include <cuda_bf16.h>

#define TLEN 2048
#define CH 8                        // elements per thread (contiguous chunk)
#define NTH 256                     // one sequence per block
#define NWARP (NTH / 32)            // 8 warps

struct M2 { float a, b, c, d; };
__device__ __forceinline__ M2 mmul(M2 X, M2 Y) {   // X*Y
    M2 r;
    r.a = fmaf(X.a, Y.a, X.b * Y.c);
    r.b = fmaf(X.a, Y.b, X.b * Y.d);
    r.c = fmaf(X.c, Y.a, X.d * Y.c);
    r.d = fmaf(X.c, Y.b, X.d * Y.d);
    return r;
}
__device__ __forceinline__ float4 m2f4(M2 X) { return make_float4(X.a, X.b, X.c, X.d); }

struct Tables {
    float4 c0;        // gd1, gd0, r1, r0
    float4 c1;        // dt, Ac, Ad, q1
    float4 c2;        // q2, 0, 0, 0
    float4 P[5];      // A^(8*2^s), s=0..4  (A^8..A^128)
    float4 W[3];      // A^(256*2^s), s=0..2 (A^256..A^1024)
    float4 ca[2];     // correction alpha_i, i=0..7
    float4 cb[2];     // correction beta_i,  i=0..7
};
__device__   Tables g_tab;     // written by prep kernel
__constant__ Tables c_tab;     // D2D-copied from g_tab; read via LDCU (off L1tex)

__global__ void prep_kernel(
    const float* p_dt, const float* p_m, const float* p_c, const float* p_k,
    const float* p_im, const float* p_is, const float* p_om, const float* p_os)
{
    const float dt = *p_dt, m = *p_m, cc = *p_c, k = *p_k;
    const float inv_m = 1.0f / m;
    const float ios   = 1.0f / (*p_os);
    const float a1 = -k * inv_m;
    const float a2 = -cc * inv_m;
    const float s1 = (*p_is) * inv_m;
    const float s0 = (*p_im) * inv_m;
    const float q1 = a1 * ios, q2 = a2 * ios, q0 = -(*p_om) * ios;

    M2 A; A.a = 1.0f; A.b = dt; A.c = dt * a1; A.d = 1.0f + dt * a2;

    g_tab.c0 = make_float4(dt * s1, dt * s0, ios * s1, fmaf(ios, s0, q0));
    g_tab.c1 = make_float4(dt, A.c, A.d, q1);
    g_tab.c2 = make_float4(q2, 0.f, 0.f, 0.f);

    // corrections (q1,q2)*A^{i+1}, i=0..7; afterwards M = A^8
    float ca[8], cb[8];
    M2 M = A;
    #pragma unroll
    for (int i = 0; i < 8; i++) {
        ca[i] = fmaf(q1, M.a, q2 * M.c);
        cb[i] = fmaf(q1, M.b, q2 * M.d);
        if (i < 7) M = mmul(A, M);
    }
    g_tab.ca[0] = make_float4(ca[0], ca[1], ca[2], ca[3]);
    g_tab.ca[1] = make_float4(ca[4], ca[5], ca[6], ca[7]);
    g_tab.cb[0] = make_float4(cb[0], cb[1], cb[2], cb[3]);
    g_tab.cb[1] = make_float4(cb[4], cb[5], cb[6], cb[7]);

    M2 Q = M;                      // A^8
    #pragma unroll
    for (int s = 0; s < 5; s++) { g_tab.P[s] = m2f4(Q); Q = mmul(Q, Q); }
    // Q = A^256 now
    #pragma unroll
    for (int s = 0; s < 3; s++) { g_tab.W[s] = m2f4(Q); Q = mmul(Q, Q); }
}

__global__ __launch_bounds__(NTH) void physics_scan_kernel(
    const float* __restrict__ u, float* __restrict__ out, int Bsz)
{
    __shared__ float2 stot[NWARP];
    __shared__ float2 sinc[NWARP];

    const int tid  = threadIdx.x;
    const int lane = tid & 31;
    const int w    = tid >> 5;

    // Scalars from constant bank (LDCU — no L1tex traffic, no address math)
    const float gd1 = c_tab.c0.x, gd0 = c_tab.c0.y, r1 = c_tab.c0.z, r0 = c_tab.c0.w;
    const float dt  = c_tab.c1.x, Ac  = c_tab.c1.y, Ad = c_tab.c1.z, q1 = c_tab.c1.w;
    const float q2  = c_tab.c2.x;

    const size_t goff = (size_t)blockIdx.x * TLEN + (size_t)tid * CH;
    float4 u0 = *reinterpret_cast<const float4*>(u + goff);
    float4 u1 = *reinterpret_cast<const float4*>(u + goff + 4);

    // ---- Pass 1: 8-step recurrence from zero state; y0 in registers ----
    float x = 0.0f, v = 0.0f;
    float4 y0, y1;
    #define STEP(UE, YE)                                               \
    {                                                                  \
        float t  = fmaf(UE, gd1, gd0);                                 \
        float vn = fmaf(Ac, x, fmaf(Ad, v, t));                        \
        float xn = fmaf(dt, v, x);                                     \
        x = xn; v = vn;                                                \
        YE = fmaf(q1, x, fmaf(q2, v, fmaf(UE, r1, r0)));               \
    }
    STEP(u0.x, y0.x) STEP(u0.y, y0.y) STEP(u0.z, y0.z) STEP(u0.w, y0.w)
    STEP(u1.x, y1.x) STEP(u1.y, y1.y) STEP(u1.z, y1.z) STEP(u1.w, y1.w)
    #undef STEP

    // ---- Warp Kogge-Stone scan of chunk offsets (matrices lane-common) ----
    float bx = x, bv = v;
    #pragma unroll
    for (int s = 0; s < 5; s++) {
        int d = 1 << s;
        const float4 Pm = c_tab.P[s];
        float ox = __shfl_up_sync(0xffffffffu, bx, d);
        float ov = __shfl_up_sync(0xffffffffu, bv, d);
        if (lane >= d) {
            bx = fmaf(Pm.x, ox, fmaf(Pm.y, ov, bx));
            bv = fmaf(Pm.z, ox, fmaf(Pm.w, ov, bv));
        }
    }
    float ex = __shfl_up_sync(0xffffffffu, bx, 1);
    float ev = __shfl_up_sync(0xffffffffu, bv, 1);
    if (lane == 0) { ex = 0.0f; ev = 0.0f; }

    if (lane == 31) stot[w] = make_float2(bx, bv);
    __syncthreads();

    // ---- Warp 0: 8-lane scan of warp totals with A^(256*2^s) ----
    if (tid < NWARP) {
        float2 t = stot[tid];
        float ix = t.x, iv = t.y;
        #pragma unroll
        for (int s = 0; s < 3; s++) {
            int d = 1 << s;
            const float4 Wm = c_tab.W[s];
            float ox = __shfl_up_sync(0x000000ffu, ix, d);
            float ov = __shfl_up_sync(0x000000ffu, iv, d);
            if (tid >= d) {
                ix = fmaf(Wm.x, ox, fmaf(Wm.y, ov, ix));
                iv = fmaf(Wm.z, ox, fmaf(Wm.w, ov, iv));
            }
        }
        float jx = __shfl_up_sync(0x000000ffu, ix, 1);
        float jv = __shfl_up_sync(0x000000ffu, iv, 1);
        if (tid == 0) { jx = 0.0f; jv = 0.0f; }
        sinc[tid] = make_float2(jx, jv);
        if (tid == NWARP - 1) {            // s_T = inclusive total (state0 = 0)
            float2* stout = reinterpret_cast<float2*>(out + (size_t)Bsz * TLEN);
            stout[blockIdx.x] = make_float2(ix, iv);
        }
    }
    __syncthreads();

    // ---- Chunk start state: A^(8*lane) * W_in + exclusive-lane offset ----
    float2 Wi = sinc[w];
    float wx = Wi.x, wv = Wi.y;
    #pragma unroll
    for (int b = 0; b < 5; b++) {
        const float4 Pm = c_tab.P[b];
        if (lane & (1 << b)) {
            float nx = fmaf(Pm.x, wx, Pm.y * wv);
            float nv = fmaf(Pm.z, wx, Pm.w * wv);
            wx = nx; wv = nv;
        }
    }
    const float sx = ex + wx, sv = ev + wv;

    // ---- Fused affine correction: y_i = y0_i + ca_i*sx + cb_i*sv ----
    const float4 caA = c_tab.ca[0], caB = c_tab.ca[1];
    const float4 cbA = c_tab.cb[0], cbB = c_tab.cb[1];

    y0.x = fmaf(caA.x, sx, fmaf(cbA.x, sv, y0.x));
    y0.y = fmaf(caA.y, sx, fmaf(cbA.y, sv, y0.y));
    y0.z = fmaf(caA.z, sx, fmaf(cbA.z, sv, y0.z));
    y0.w = fmaf(caA.w, sx, fmaf(cbA.w, sv, y0.w));
    y1.x = fmaf(caB.x, sx, fmaf(cbB.x, sv, y1.x));
    y1.y = fmaf(caB.y, sx, fmaf(cbB.y, sv, y1.y));
    y1.z = fmaf(caB.z, sx, fmaf(cbB.z, sv, y1.z));
    y1.w = fmaf(caB.w, sx, fmaf(cbB.w, sv, y1.w));

    *reinterpret_cast<float4*>(out + goff)     = y0;
    *reinterpret_cast<float4*>(out + goff + 4) = y1;
}

extern "C" void kernel_launch(void* const* d_in, const int* in_sizes, int n_in,
                              void* d_out, int out_size) {
    const float* u = (const float*)d_in[0];
    int Bsz = in_sizes[0] / TLEN;

    prep_kernel<<<1, 1>>>(
        (const float*)d_in[1], (const float*)d_in[2], (const float*)d_in[3],
        (const float*)d_in[4], (const float*)d_in[5], (const float*)d_in[6],
        (const float*)d_in[7], (const float*)d_in[8]);

    // Publish the table to the constant bank (graph-capturable async D2D copy)
    void* src = nullptr;
    cudaGetSymbolAddress(&src, g_tab);
    cudaMemcpyToSymbolAsync(c_tab, src, sizeof(Tables), 0,
                            cudaMemcpyDeviceToDevice, 0);

    physics_scan_kernel<<<Bsz, NTH>>>(u, (float*)d_out, Bsz);
}